// round 14
// baseline (speedup 1.0000x reference)
#include <cuda_runtime.h>
#include <cuda_bf16.h>
#include <cstdint>

#define N_NODES 50000
#define N_EDGES 500000
#define HIDDEN  128
#define HEADS   8
#define HDIM    16

// ---------------- static device scratch ----------------
__device__ float g_q[N_NODES * HIDDEN];
__device__ float g_k[N_NODES * HIDDEN];
__device__ float g_v[N_NODES * HIDDEN];
__device__ float g_ex[N_EDGES * HEADS];
__device__ float g_s[N_NODES * HEADS];
__device__ float g_U[N_NODES * HIDDEN];
__device__ float g_disp[N_NODES * 3];
__device__ float g_gate[N_NODES];

// ---------------- packed-f32x2 + cp.async helpers ----------------
__device__ __forceinline__ uint64_t pack_dup(float a) {
    uint64_t r;
    asm("mov.b64 %0, {%1, %1};" : "=l"(r) : "f"(a));
    return r;
}
__device__ __forceinline__ void fma2(uint64_t& c, uint64_t a, uint64_t b) {
    asm("fma.rn.f32x2 %0, %1, %2, %0;" : "+l"(c) : "l"(a), "l"(b));
}
__device__ __forceinline__ float2 unpack2(uint64_t p) {
    float lo, hi;
    asm("mov.b64 {%0, %1}, %2;" : "=f"(lo), "=f"(hi) : "l"(p));
    return make_float2(lo, hi);
}
__device__ __forceinline__ uint32_t smem_u32(const void* p) {
    uint32_t a;
    asm("{ .reg .u64 t; cvta.to.shared.u64 t, %1; cvt.u32.u64 %0, t; }" : "=r"(a) : "l"(p));
    return a;
}
__device__ __forceinline__ void cp16(uint32_t dst, const void* src) {
    asm volatile("cp.async.ca.shared.global [%0], [%1], 16;" :: "r"(dst), "l"(src) : "memory");
}
__device__ __forceinline__ void cp_commit() { asm volatile("cp.async.commit_group;" ::: "memory"); }
__device__ __forceinline__ void cp_wait1() { asm volatile("cp.async.wait_group 1;" ::: "memory"); }
__device__ __forceinline__ void cp_wait0() { asm volatile("cp.async.wait_group 0;" ::: "memory"); }

// ---------------- GEMM core: 64x128 tile, 256 thr, 4x8 microtile ----------------
struct __align__(16) SmemBufs {
    float As[2][64][20];    // row-major A chunk (80B row stride)
    float Bs[2][16][128];
};

__device__ __forceinline__ void load_chunk(SmemBufs& S, int buf, int c,
    const float* __restrict__ A, const float* __restrict__ B, int row0, int M, int t)
{
    {   // A: 64 rows x 4 float4 = 256 slots
        int r = t >> 2, q = t & 3;
        int gr = min(row0 + r, M - 1);
        cp16(smem_u32(&S.As[buf][r][q * 4]), A + gr * HIDDEN + c * 16 + q * 4);
    }
#pragma unroll
    for (int it = 0; it < 2; it++) {   // B: 16 x 32 float4 = 512 slots
        int s = t + it * 256;
        int r = s >> 5, q = s & 31;
        cp16(smem_u32(&S.Bs[buf][r][q * 4]), B + (c * 16 + r) * HIDDEN + q * 4);
    }
}

// tx = t&15 (cols tx*8..tx*8+7), ty = t>>4 (rows ty*4..ty*4+3)
template <bool SCALE>
__device__ __forceinline__ void run_gemm(SmemBufs& S,
    const float* __restrict__ A, const float* __restrict__ B,
    int row0, int M, int t, int tx, int ty, uint64_t acc[4][4])
{
#pragma unroll
    for (int i = 0; i < 4; i++)
#pragma unroll
        for (int j = 0; j < 4; j++) acc[i][j] = 0ull;

    load_chunk(S, 0, 0, A, B, row0, M, t);
    cp_commit();

    for (int c = 0; c < 8; c++) {
        if (c < 7) { load_chunk(S, (c + 1) & 1, c + 1, A, B, row0, M, t); cp_commit(); }
        if (c < 7) cp_wait1(); else cp_wait0();
        __syncthreads();

        float inv[4];
        if (SCALE) {
#pragma unroll
            for (int i = 0; i < 4; i++) {
                int gr = min(row0 + ty * 4 + i, M - 1);
                inv[i] = __frcp_rn(fmaxf(g_s[gr * HEADS + c], 1e-9f));
            }
        }

        const int buf = c & 1;
#pragma unroll
        for (int kk = 0; kk < 16; kk++) {
            ulonglong2 b01 = *(ulonglong2*)(&S.Bs[buf][kk][tx * 8]);
            ulonglong2 b23 = *(ulonglong2*)(&S.Bs[buf][kk][tx * 8 + 4]);
            uint64_t bp[4] = {b01.x, b01.y, b23.x, b23.y};
#pragma unroll
            for (int i = 0; i < 4; i++) {
                float a = S.As[buf][ty * 4 + i][kk];
                if (SCALE) a *= inv[i];
                uint64_t ap = pack_dup(a);
#pragma unroll
                for (int j = 0; j < 4; j++) fma2(acc[i][j], ap, bp[j]);
            }
        }
        __syncthreads();
    }
}

// ================= QKV GEMM + fused scratch init =================
__global__ __launch_bounds__(256, 3) void gemm_qkv(
    const float* __restrict__ A,
    const float* __restrict__ B0, const float* __restrict__ B1, const float* __restrict__ B2,
    const float* __restrict__ bias0, const float* __restrict__ bias1, const float* __restrict__ bias2,
    float* __restrict__ out0, float* __restrict__ out1, float* __restrict__ out2,
    int M)
{
    __shared__ SmemBufs S;

    {
        int nthr = gridDim.x * gridDim.y * 256;
        int gtid = (blockIdx.y * gridDim.x + blockIdx.x) * 256 + threadIdx.x;
        float4 z = make_float4(0.f, 0.f, 0.f, 0.f);
        for (int i = gtid; i < N_NODES * HIDDEN / 4; i += nthr) ((float4*)g_U)[i] = z;
        for (int i = gtid; i < N_NODES * HEADS / 4; i += nthr) ((float4*)g_s)[i] = z;
        for (int i = gtid; i < N_NODES * 3 / 4; i += nthr) ((float4*)g_disp)[i] = z;
    }

    const float* B    = (blockIdx.y == 0) ? B0    : (blockIdx.y == 1) ? B1    : B2;
    const float* bias = (blockIdx.y == 0) ? bias0 : (blockIdx.y == 1) ? bias1 : bias2;
    float*       out  = (blockIdx.y == 0) ? out0  : (blockIdx.y == 1) ? out1  : out2;

    const int t = threadIdx.x, tx = t & 15, ty = t >> 4;
    const int row0 = blockIdx.x * 64;

    uint64_t acc[4][4];
    run_gemm<false>(S, A, B, row0, M, t, tx, ty, acc);

#pragma unroll
    for (int i = 0; i < 4; i++) {
        int gr = row0 + ty * 4 + i;
        if (gr >= M) continue;
#pragma unroll
        for (int jj = 0; jj < 2; jj++) {
            int col = tx * 8 + jj * 4;
            float2 p0 = unpack2(acc[i][jj * 2 + 0]);
            float2 p1 = unpack2(acc[i][jj * 2 + 1]);
            *(float4*)(out + gr * HIDDEN + col) =
                make_float4(p0.x + bias[col], p0.y + bias[col + 1],
                            p1.x + bias[col + 2], p1.y + bias[col + 3]);
        }
    }
}

// ================= fused node epilogue =================
__global__ __launch_bounds__(256, 3) void k_node_out(
    const float* __restrict__ Wo, const float* __restrict__ bo,
    const float* __restrict__ Wg1, const float* __restrict__ bg1,
    const float* __restrict__ Wg2, const float* __restrict__ bg2,
    const float* __restrict__ hres,
    float* __restrict__ out, int M)
{
    __shared__ SmemBufs S;
    const int t = threadIdx.x, tx = t & 15, ty = t >> 4;
    const int row0 = blockIdx.x * 64;

    uint64_t acc[4][4];

    // ---- stage 1: h_out = hupd @ Wo + bo + h ----
    run_gemm<true>(S, g_U, Wo, row0, M, t, tx, ty, acc);
#pragma unroll
    for (int i = 0; i < 4; i++) {
        int gr = row0 + ty * 4 + i;
        if (gr >= M) continue;
#pragma unroll
        for (int jj = 0; jj < 2; jj++) {
            int col = tx * 8 + jj * 4;
            float2 p0 = unpack2(acc[i][jj * 2 + 0]);
            float2 p1 = unpack2(acc[i][jj * 2 + 1]);
            float4 r4 = *(const float4*)(hres + gr * HIDDEN + col);
            *(float4*)(out + gr * HIDDEN + col) =
                make_float4(p0.x + bo[col] + r4.x, p0.y + bo[col + 1] + r4.y,
                            p1.x + bo[col + 2] + r4.z, p1.y + bo[col + 3] + r4.w);
        }
    }
    __syncthreads();

    // ---- stage 2: t1 = silu(h_out @ Wg1 + bg1) ----
    run_gemm<false>(S, out, Wg1, row0, M, t, tx, ty, acc);

    // ---- stage 3: gate = tanh(t1 . Wg2 + bg2) ----
    float w2[8];
#pragma unroll
    for (int j = 0; j < 8; j++) w2[j] = Wg2[tx * 8 + j];
    const float bg2v = bg2[0];

#pragma unroll
    for (int i = 0; i < 4; i++) {
        float p = 0.f;
#pragma unroll
        for (int j = 0; j < 4; j++) {
            float2 v = unpack2(acc[i][j]);
            float t0 = v.x + bg1[tx * 8 + j * 2];
            float t1v = v.y + bg1[tx * 8 + j * 2 + 1];
            t0 = t0 / (1.f + __expf(-t0));
            t1v = t1v / (1.f + __expf(-t1v));
            p = fmaf(t0, w2[j * 2], p);
            p = fmaf(t1v, w2[j * 2 + 1], p);
        }
#pragma unroll
        for (int off = 1; off < 16; off <<= 1)
            p += __shfl_xor_sync(0xffffffffu, p, off);
        if (tx == 0) {
            int gr = row0 + ty * 4 + i;
            if (gr < M) g_gate[gr] = tanhf(p + bg2v);
        }
    }
}

// ---------------- x_out epilogue ----------------
__global__ void k_xout(const float* __restrict__ x, float* __restrict__ out)
{
    int i = blockIdx.x * blockDim.x + threadIdx.x;
    if (i >= N_NODES * 3) return;
    int node = i / 3;
    out[N_NODES * HIDDEN + i] = x[i] + g_gate[node] * g_disp[i];
}

// ---------------- fused edge kernel: head-pair per thread ----------------
__global__ __launch_bounds__(256) void k_edge(
    const int* __restrict__ src, const int* __restrict__ dst,
    const float* __restrict__ dist,
    const float* __restrict__ Wd, const float* __restrict__ bd)
{
    int gt = blockIdx.x * blockDim.x + threadIdx.x;
    if (gt >= N_EDGES * 4) return;          // 2M threads, 2 heads each
    int e = gt >> 2, hp = (gt & 3) << 1;    // head pair {hp, hp+1}
    int sn = src[e], dn = dst[e];

    const float4* qp = (const float4*)(g_q + sn * HIDDEN + hp * HDIM);  // 8 float4
    const float4* kp = (const float4*)(g_k + dn * HIDDEN + hp * HDIM);
    float4 q[8], k[8];
#pragma unroll
    for (int i = 0; i < 8; i++) { q[i] = qp[i]; k[i] = kp[i]; }

    float a0 = 0.f, a1 = 0.f;
#pragma unroll
    for (int i = 0; i < 4; i++) {
        a0 += q[i].x * k[i].x + q[i].y * k[i].y + q[i].z * k[i].z + q[i].w * k[i].w;
        a1 += q[i+4].x * k[i+4].x + q[i+4].y * k[i+4].y + q[i+4].z * k[i+4].z + q[i+4].w * k[i+4].w;
    }
    float dd = dist[e], dd2 = dd * dd;
    float ex0 = __expf(a0 * 0.25f - (dd2 * Wd[hp]     + bd[hp]));
    float ex1 = __expf(a1 * 0.25f - (dd2 * Wd[hp + 1] + bd[hp + 1]));

    *(float2*)(g_ex + e * 8 + hp) = make_float2(ex0, ex1);

    asm volatile("red.global.add.v2.f32 [%0], {%1,%2};"
                 :: "l"(g_s + sn * HEADS + hp), "f"(ex0), "f"(ex1) : "memory");

    const float4* vp = (const float4*)(g_v + dn * HIDDEN + hp * HDIM);
    float* up = g_U + sn * HIDDEN + hp * HDIM;
#pragma unroll
    for (int i = 0; i < 8; i++) {
        float ex = (i < 4) ? ex0 : ex1;
        float4 vv = vp[i];
        float x0 = vv.x * ex, x1 = vv.y * ex, x2 = vv.z * ex, x3 = vv.w * ex;
        asm volatile("red.global.add.v4.f32 [%0], {%1,%2,%3,%4};"
                     :: "l"(up + i * 4), "f"(x0), "f"(x1), "f"(x2), "f"(x3)
                     : "memory");
    }
}

// ---------------- displacement scatter ----------------
__global__ void k_disp(const int* __restrict__ src, const int* __restrict__ dst,
                       const float* __restrict__ x)
{
    int e = blockIdx.x * blockDim.x + threadIdx.x;
    if (e >= N_EDGES) return;
    int sn = src[e], dn = dst[e];

    const float4* exp4 = (const float4*)(g_ex + e * 8);
    const float4* sp   = (const float4*)(g_s + sn * 8);
    float4 e0 = exp4[0], e1 = exp4[1];
    float4 s0 = sp[0],   s1 = sp[1];

    float wsum =
        e0.x / fmaxf(s0.x, 1e-9f) + e0.y / fmaxf(s0.y, 1e-9f) +
        e0.z / fmaxf(s0.z, 1e-9f) + e0.w / fmaxf(s0.w, 1e-9f) +
        e1.x / fmaxf(s1.x, 1e-9f) + e1.y / fmaxf(s1.y, 1e-9f) +
        e1.z / fmaxf(s1.z, 1e-9f) + e1.w / fmaxf(s1.w, 1e-9f);
    float wmean = wsum * 0.125f;

#pragma unroll
    for (int c = 0; c < 3; c++)
        atomicAdd(&g_disp[sn * 3 + c], (x[dn * 3 + c] - x[sn * 3 + c]) * wmean);
}

// ---------------- launch ----------------
extern "C" void kernel_launch(void* const* d_in, const int* in_sizes, int n_in,
                              void* d_out, int out_size)
{
    (void)in_sizes; (void)n_in; (void)out_size;
    const float* h    = (const float*)d_in[0];
    const float* x    = (const float*)d_in[1];
    const int*   src  = (const int*)  d_in[2];
    const int*   dst  = (const int*)  d_in[3];
    const float* dist = (const float*)d_in[4];
    const float* Wq = (const float*)d_in[5],  *bq = (const float*)d_in[6];
    const float* Wk = (const float*)d_in[7],  *bk = (const float*)d_in[8];
    const float* Wv = (const float*)d_in[9],  *bv = (const float*)d_in[10];
    const float* Wo = (const float*)d_in[11], *bo = (const float*)d_in[12];
    const float* Wd = (const float*)d_in[13], *bd = (const float*)d_in[14];
    const float* Wg1 = (const float*)d_in[15], *bg1 = (const float*)d_in[16];
    const float* Wg2 = (const float*)d_in[17], *bg2 = (const float*)d_in[18];
    float* out = (float*)d_out;

    void *pq, *pk, *pv;
    cudaGetSymbolAddress(&pq, g_q);
    cudaGetSymbolAddress(&pk, g_k);
    cudaGetSymbolAddress(&pv, g_v);
    float* fq = (float*)pq; float* fk = (float*)pk; float* fv = (float*)pv;

    static cudaStream_t s2 = nullptr;
    static cudaEvent_t ev_fork = nullptr, ev_join = nullptr;
    if (s2 == nullptr) {
        cudaStreamCreateWithFlags(&s2, cudaStreamNonBlocking);
        cudaEventCreateWithFlags(&ev_fork, cudaEventDisableTiming);
        cudaEventCreateWithFlags(&ev_join, cudaEventDisableTiming);
    }

    const int B = 256;
    int gblocks = (N_NODES + 63) / 64;      // 64-row tiles -> 782 CTAs

    // fused QKV projection + scratch zero-init
    {
        dim3 grid(gblocks, 3);
        gemm_qkv<<<grid, 256>>>(h, Wq, Wk, Wv, bq, bk, bv, fq, fk, fv, N_NODES);
    }

    // edge phase (head-pair per thread)
    int npair = N_EDGES * 4;
    k_edge<<<(npair + B - 1) / B, B>>>(src, dst, dist, Wd, bd);

    // fork: k_disp on side stream
    cudaEventRecord(ev_fork, 0);
    cudaStreamWaitEvent(s2, ev_fork, 0);
    k_disp<<<(N_EDGES + B - 1) / B, B, 0, s2>>>(src, dst, x);
    cudaEventRecord(ev_join, s2);

    // fused node epilogue on main stream
    k_node_out<<<gblocks, 256>>>(Wo, bo, Wg1, bg1, Wg2, bg2, h, out, N_NODES);

    cudaStreamWaitEvent(0, ev_join, 0);
    k_xout<<<(N_NODES * 3 + B - 1) / B, B>>>(x, out);
}

// round 15
// speedup vs baseline: 1.5995x; 1.5995x over previous
#include <cuda_runtime.h>
#include <cuda_bf16.h>
#include <cstdint>

#define N_NODES 50000
#define N_EDGES 500000
#define HIDDEN  128
#define HEADS   8
#define HDIM    16

// ---------------- static device scratch ----------------
__device__ float g_q[N_NODES * HIDDEN];
__device__ float g_k[N_NODES * HIDDEN];
__device__ float g_v[N_NODES * HIDDEN];
__device__ float g_ex[N_EDGES * HEADS];
__device__ float g_s[N_NODES * HEADS];
__device__ float g_U[N_NODES * HIDDEN];
__device__ float g_disp[N_NODES * 3];
__device__ float g_gate[N_NODES];

// ---------------- packed-f32x2 + cp.async helpers ----------------
__device__ __forceinline__ uint64_t pack_dup(float a) {
    uint64_t r;
    asm("mov.b64 %0, {%1, %1};" : "=l"(r) : "f"(a));
    return r;
}
__device__ __forceinline__ void fma2(uint64_t& c, uint64_t a, uint64_t b) {
    asm("fma.rn.f32x2 %0, %1, %2, %0;" : "+l"(c) : "l"(a), "l"(b));
}
__device__ __forceinline__ float2 unpack2(uint64_t p) {
    float lo, hi;
    asm("mov.b64 {%0, %1}, %2;" : "=f"(lo), "=f"(hi) : "l"(p));
    return make_float2(lo, hi);
}
__device__ __forceinline__ uint32_t smem_u32(const void* p) {
    uint32_t a;
    asm("{ .reg .u64 t; cvta.to.shared.u64 t, %1; cvt.u32.u64 %0, t; }" : "=r"(a) : "l"(p));
    return a;
}
__device__ __forceinline__ void cp16(uint32_t dst, const void* src) {
    asm volatile("cp.async.ca.shared.global [%0], [%1], 16;" :: "r"(dst), "l"(src) : "memory");
}
__device__ __forceinline__ void cp_commit() { asm volatile("cp.async.commit_group;" ::: "memory"); }
__device__ __forceinline__ void cp_wait1() { asm volatile("cp.async.wait_group 1;" ::: "memory"); }
__device__ __forceinline__ void cp_wait0() { asm volatile("cp.async.wait_group 0;" ::: "memory"); }

// ---------------- GEMM core (R11-proven): 128x128 tile, 256 thr, 8x8 ----------------
struct __align__(16) SmemBufs {
    float As[2][128][20];
    float Bs[2][16][128];
};

__device__ __forceinline__ void load_chunk(SmemBufs& S, int buf, int c,
    const float* __restrict__ A, const float* __restrict__ B, int row0, int M, int t)
{
#pragma unroll
    for (int it = 0; it < 2; it++) {
        int s = t + it * 256;
        int r = s >> 2, q = s & 3;
        int gr = min(row0 + r, M - 1);
        cp16(smem_u32(&S.As[buf][r][q * 4]), A + gr * HIDDEN + c * 16 + q * 4);
    }
#pragma unroll
    for (int it = 0; it < 2; it++) {
        int s = t + it * 256;
        int r = s >> 5, q = s & 31;
        cp16(smem_u32(&S.Bs[buf][r][q * 4]), B + (c * 16 + r) * HIDDEN + q * 4);
    }
}

template <bool SCALE>
__device__ __forceinline__ void run_gemm(SmemBufs& S,
    const float* __restrict__ A, const float* __restrict__ B,
    int row0, int M, int t, int tx, int ty, uint64_t acc[8][4])
{
#pragma unroll
    for (int i = 0; i < 8; i++)
#pragma unroll
        for (int j = 0; j < 4; j++) acc[i][j] = 0ull;

    load_chunk(S, 0, 0, A, B, row0, M, t);
    cp_commit();

    for (int c = 0; c < 8; c++) {
        if (c < 7) { load_chunk(S, (c + 1) & 1, c + 1, A, B, row0, M, t); cp_commit(); }
        if (c < 7) cp_wait1(); else cp_wait0();
        __syncthreads();

        float inv[8];
        if (SCALE) {
#pragma unroll
            for (int i = 0; i < 8; i++) {
                int gr = min(row0 + ty * 8 + i, M - 1);
                inv[i] = __frcp_rn(fmaxf(g_s[gr * HEADS + c], 1e-9f));
            }
        }

        const int buf = c & 1;
#pragma unroll
        for (int kk = 0; kk < 16; kk++) {
            ulonglong2 b01 = *(ulonglong2*)(&S.Bs[buf][kk][tx * 8]);
            ulonglong2 b23 = *(ulonglong2*)(&S.Bs[buf][kk][tx * 8 + 4]);
            uint64_t bp[4] = {b01.x, b01.y, b23.x, b23.y};
            uint64_t ap[8];
#pragma unroll
            for (int i = 0; i < 8; i++) {
                float a = S.As[buf][ty * 8 + i][kk];
                if (SCALE) a *= inv[i];
                ap[i] = pack_dup(a);
            }
#pragma unroll
            for (int i = 0; i < 8; i++)
#pragma unroll
                for (int j = 0; j < 4; j++) fma2(acc[i][j], ap[i], bp[j]);
        }
        __syncthreads();
    }
}

// ================= QKV GEMM + fused scratch init =================
__global__ __launch_bounds__(256, 2) void gemm_qkv(
    const float* __restrict__ A,
    const float* __restrict__ B0, const float* __restrict__ B1, const float* __restrict__ B2,
    const float* __restrict__ bias0, const float* __restrict__ bias1, const float* __restrict__ bias2,
    float* __restrict__ out0, float* __restrict__ out1, float* __restrict__ out2,
    int M)
{
    __shared__ SmemBufs S;

    {
        int nthr = gridDim.x * gridDim.y * 256;
        int gtid = (blockIdx.y * gridDim.x + blockIdx.x) * 256 + threadIdx.x;
        float4 z = make_float4(0.f, 0.f, 0.f, 0.f);
        for (int i = gtid; i < N_NODES * HIDDEN / 4; i += nthr) ((float4*)g_U)[i] = z;
        for (int i = gtid; i < N_NODES * HEADS / 4; i += nthr) ((float4*)g_s)[i] = z;
        for (int i = gtid; i < N_NODES * 3 / 4; i += nthr) ((float4*)g_disp)[i] = z;
    }

    const float* B    = (blockIdx.y == 0) ? B0    : (blockIdx.y == 1) ? B1    : B2;
    const float* bias = (blockIdx.y == 0) ? bias0 : (blockIdx.y == 1) ? bias1 : bias2;
    float*       out  = (blockIdx.y == 0) ? out0  : (blockIdx.y == 1) ? out1  : out2;

    const int t = threadIdx.x, tx = t & 15, ty = t >> 4;
    const int row0 = blockIdx.x * 128;

    uint64_t acc[8][4];
    run_gemm<false>(S, A, B, row0, M, t, tx, ty, acc);

#pragma unroll
    for (int i = 0; i < 8; i++) {
        int gr = row0 + ty * 8 + i;
        if (gr >= M) continue;
#pragma unroll
        for (int jj = 0; jj < 2; jj++) {
            int col = tx * 8 + jj * 4;
            float2 p0 = unpack2(acc[i][jj * 2 + 0]);
            float2 p1 = unpack2(acc[i][jj * 2 + 1]);
            *(float4*)(out + gr * HIDDEN + col) =
                make_float4(p0.x + bias[col], p0.y + bias[col + 1],
                            p1.x + bias[col + 2], p1.y + bias[col + 3]);
        }
    }
}

// ================= fused node epilogue (gate only; x_out deferred) =================
__global__ __launch_bounds__(256, 2) void k_node_out(
    const float* __restrict__ Wo, const float* __restrict__ bo,
    const float* __restrict__ Wg1, const float* __restrict__ bg1,
    const float* __restrict__ Wg2, const float* __restrict__ bg2,
    const float* __restrict__ hres,
    float* __restrict__ out, int M)
{
    __shared__ SmemBufs S;
    const int t = threadIdx.x, tx = t & 15, ty = t >> 4;
    const int row0 = blockIdx.x * 128;

    uint64_t acc[8][4];

    // ---- stage 1: h_out = hupd @ Wo + bo + h ----
    run_gemm<true>(S, g_U, Wo, row0, M, t, tx, ty, acc);
#pragma unroll
    for (int i = 0; i < 8; i++) {
        int gr = row0 + ty * 8 + i;
        if (gr >= M) continue;
#pragma unroll
        for (int jj = 0; jj < 2; jj++) {
            int col = tx * 8 + jj * 4;
            float2 p0 = unpack2(acc[i][jj * 2 + 0]);
            float2 p1 = unpack2(acc[i][jj * 2 + 1]);
            float4 r4 = *(const float4*)(hres + gr * HIDDEN + col);
            *(float4*)(out + gr * HIDDEN + col) =
                make_float4(p0.x + bo[col] + r4.x, p0.y + bo[col + 1] + r4.y,
                            p1.x + bo[col + 2] + r4.z, p1.y + bo[col + 3] + r4.w);
        }
    }
    __syncthreads();

    // ---- stage 2: t1 = silu(h_out @ Wg1 + bg1) ----
    run_gemm<false>(S, out, Wg1, row0, M, t, tx, ty, acc);

    // ---- stage 3: gate = tanh(t1 . Wg2 + bg2) ----
    float w2[8];
#pragma unroll
    for (int j = 0; j < 8; j++) w2[j] = Wg2[tx * 8 + j];
    const float bg2v = bg2[0];

#pragma unroll
    for (int i = 0; i < 8; i++) {
        float p = 0.f;
#pragma unroll
        for (int j = 0; j < 4; j++) {
            float2 v = unpack2(acc[i][j]);
            float t0 = v.x + bg1[tx * 8 + j * 2];
            float t1v = v.y + bg1[tx * 8 + j * 2 + 1];
            t0 = t0 / (1.f + __expf(-t0));
            t1v = t1v / (1.f + __expf(-t1v));
            p = fmaf(t0, w2[j * 2], p);
            p = fmaf(t1v, w2[j * 2 + 1], p);
        }
#pragma unroll
        for (int off = 1; off < 16; off <<= 1)
            p += __shfl_xor_sync(0xffffffffu, p, off);
        if (tx == 0) {
            int gr = row0 + ty * 8 + i;
            if (gr < M) g_gate[gr] = tanhf(p + bg2v);
        }
    }
}

// ---------------- x_out epilogue ----------------
__global__ void k_xout(const float* __restrict__ x, float* __restrict__ out)
{
    int i = blockIdx.x * blockDim.x + threadIdx.x;
    if (i >= N_NODES * 3) return;
    int node = i / 3;
    out[N_NODES * HIDDEN + i] = x[i] + g_gate[node] * g_disp[i];
}

// ---------------- warp-per-edge kernel: 1 coalesced REDG.128 per edge ----------------
// lane = h*4 + c: 8 heads x 4 float4 chunks cover the 128-float row.
__global__ __launch_bounds__(256) void k_edge(
    const int* __restrict__ src, const int* __restrict__ dst,
    const float* __restrict__ dist,
    const float* __restrict__ Wd, const float* __restrict__ bd)
{
    int e = (blockIdx.x * blockDim.x + threadIdx.x) >> 5;
    if (e >= N_EDGES) return;
    const int lane = threadIdx.x & 31;
    const int h = lane >> 2;

    int sn = src[e], dn = dst[e];

    float4 q4 = *(const float4*)(g_q + sn * HIDDEN + lane * 4);
    float4 k4 = *(const float4*)(g_k + dn * HIDDEN + lane * 4);
    float p = q4.x * k4.x + q4.y * k4.y + q4.z * k4.z + q4.w * k4.w;
    p += __shfl_xor_sync(0xffffffffu, p, 1);
    p += __shfl_xor_sync(0xffffffffu, p, 2);   // per-head dot, replicated in quad

    float dd = dist[e];
    float lg = p * 0.25f - (dd * dd * Wd[h] + bd[h]);
    float ex = __expf(lg);

    if ((lane & 3) == 0) {
        g_ex[e * 8 + h] = ex;
        asm volatile("red.global.add.f32 [%0], %1;"
                     :: "l"(g_s + sn * HEADS + h), "f"(ex) : "memory");
    }

    float4 v4 = *(const float4*)(g_v + dn * HIDDEN + lane * 4);
    float x0 = v4.x * ex, x1 = v4.y * ex, x2 = v4.z * ex, x3 = v4.w * ex;
    asm volatile("red.global.add.v4.f32 [%0], {%1,%2,%3,%4};"
                 :: "l"(g_U + sn * HIDDEN + lane * 4), "f"(x0), "f"(x1), "f"(x2), "f"(x3)
                 : "memory");
}

// ---------------- displacement scatter ----------------
__global__ void k_disp(const int* __restrict__ src, const int* __restrict__ dst,
                       const float* __restrict__ x)
{
    int e = blockIdx.x * blockDim.x + threadIdx.x;
    if (e >= N_EDGES) return;
    int sn = src[e], dn = dst[e];

    const float4* exp4 = (const float4*)(g_ex + e * 8);
    const float4* sp   = (const float4*)(g_s + sn * 8);
    float4 e0 = exp4[0], e1 = exp4[1];
    float4 s0 = sp[0],   s1 = sp[1];

    float wsum =
        e0.x / fmaxf(s0.x, 1e-9f) + e0.y / fmaxf(s0.y, 1e-9f) +
        e0.z / fmaxf(s0.z, 1e-9f) + e0.w / fmaxf(s0.w, 1e-9f) +
        e1.x / fmaxf(s1.x, 1e-9f) + e1.y / fmaxf(s1.y, 1e-9f) +
        e1.z / fmaxf(s1.z, 1e-9f) + e1.w / fmaxf(s1.w, 1e-9f);
    float wmean = wsum * 0.125f;

#pragma unroll
    for (int c = 0; c < 3; c++)
        atomicAdd(&g_disp[sn * 3 + c], (x[dn * 3 + c] - x[sn * 3 + c]) * wmean);
}

// ---------------- launch ----------------
extern "C" void kernel_launch(void* const* d_in, const int* in_sizes, int n_in,
                              void* d_out, int out_size)
{
    (void)in_sizes; (void)n_in; (void)out_size;
    const float* h    = (const float*)d_in[0];
    const float* x    = (const float*)d_in[1];
    const int*   src  = (const int*)  d_in[2];
    const int*   dst  = (const int*)  d_in[3];
    const float* dist = (const float*)d_in[4];
    const float* Wq = (const float*)d_in[5],  *bq = (const float*)d_in[6];
    const float* Wk = (const float*)d_in[7],  *bk = (const float*)d_in[8];
    const float* Wv = (const float*)d_in[9],  *bv = (const float*)d_in[10];
    const float* Wo = (const float*)d_in[11], *bo = (const float*)d_in[12];
    const float* Wd = (const float*)d_in[13], *bd = (const float*)d_in[14];
    const float* Wg1 = (const float*)d_in[15], *bg1 = (const float*)d_in[16];
    const float* Wg2 = (const float*)d_in[17], *bg2 = (const float*)d_in[18];
    float* out = (float*)d_out;

    void *pq, *pk, *pv;
    cudaGetSymbolAddress(&pq, g_q);
    cudaGetSymbolAddress(&pk, g_k);
    cudaGetSymbolAddress(&pv, g_v);
    float* fq = (float*)pq; float* fk = (float*)pk; float* fv = (float*)pv;

    static cudaStream_t s2 = nullptr;
    static cudaEvent_t ev_fork = nullptr, ev_join = nullptr;
    if (s2 == nullptr) {
        cudaStreamCreateWithFlags(&s2, cudaStreamNonBlocking);
        cudaEventCreateWithFlags(&ev_fork, cudaEventDisableTiming);
        cudaEventCreateWithFlags(&ev_join, cudaEventDisableTiming);
    }

    const int B = 256;
    int gblocks = (N_NODES + 127) / 128;

    // fused QKV projection + scratch zero-init
    {
        dim3 grid(gblocks, 3);
        gemm_qkv<<<grid, 256>>>(h, Wq, Wk, Wv, bq, bk, bv, fq, fk, fv, N_NODES);
    }

    // edge phase: warp per edge
    {
        long long nthreads = (long long)N_EDGES * 32;
        k_edge<<<(int)((nthreads + B - 1) / B), B>>>(src, dst, dist, Wd, bd);
    }

    // fork: k_disp on side stream
    cudaEventRecord(ev_fork, 0);
    cudaStreamWaitEvent(s2, ev_fork, 0);
    k_disp<<<(N_EDGES + B - 1) / B, B, 0, s2>>>(src, dst, x);
    cudaEventRecord(ev_join, s2);

    // fused node epilogue on main stream
    k_node_out<<<gblocks, 256>>>(Wo, bo, Wg1, bg1, Wg2, bg2, h, out, N_NODES);

    cudaStreamWaitEvent(0, ev_join, 0);
    k_xout<<<(N_NODES * 3 + B - 1) / B, B>>>(x, out);
}

// round 17
// speedup vs baseline: 2.2437x; 1.4027x over previous
#include <cuda_runtime.h>
#include <cuda_bf16.h>
#include <cstdint>

#define N_NODES 50000
#define N_EDGES 500000
#define HIDDEN  128
#define HEADS   8
#define HDIM    16

// ---------------- static device scratch ----------------
__device__ float g_q[N_NODES * HIDDEN];
__device__ float g_k[N_NODES * HIDDEN];
__device__ float g_v[N_NODES * HIDDEN];
__device__ float g_ex[N_EDGES * HEADS];
__device__ float g_s[N_NODES * HEADS];
__device__ float g_U[N_NODES * HIDDEN];
__device__ float g_disp[N_NODES * 3];
__device__ float g_gate[N_NODES];
// pre-converted weights: [mat][n][k] hi/lo bf16 (mat: 0=Wq 1=Wk 2=Wv 3=Wo 4=Wg1)
__device__ __nv_bfloat16 g_Wh[5 * 128 * 128];
__device__ __nv_bfloat16 g_Wl[5 * 128 * 128];

// ---------------- helpers ----------------
__device__ __forceinline__ uint32_t smem_u32(const void* p) {
    uint32_t a;
    asm("{ .reg .u64 t; cvta.to.shared.u64 t, %1; cvt.u32.u64 %0, t; }" : "=r"(a) : "l"(p));
    return a;
}
__device__ __forceinline__ void cp16(uint32_t dst, const void* src) {
    asm volatile("cp.async.ca.shared.global [%0], [%1], 16;" :: "r"(dst), "l"(src) : "memory");
}
__device__ __forceinline__ void cp_commit() { asm volatile("cp.async.commit_group;" ::: "memory"); }
__device__ __forceinline__ void cp_wait1() { asm volatile("cp.async.wait_group 1;" ::: "memory"); }
__device__ __forceinline__ void cp_wait0() { asm volatile("cp.async.wait_group 0;" ::: "memory"); }

__device__ __forceinline__ void ldmat_x4(uint32_t* r, uint32_t addr) {
    asm volatile("ldmatrix.sync.aligned.m8n8.x4.shared.b16 {%0,%1,%2,%3}, [%4];"
                 : "=r"(r[0]), "=r"(r[1]), "=r"(r[2]), "=r"(r[3]) : "r"(addr));
}
__device__ __forceinline__ void ldmat_x2(uint32_t* r, uint32_t addr) {
    asm volatile("ldmatrix.sync.aligned.m8n8.x2.shared.b16 {%0,%1}, [%2];"
                 : "=r"(r[0]), "=r"(r[1]) : "r"(addr));
}
__device__ __forceinline__ void mma16816(float* c, const uint32_t* a, const uint32_t* b) {
    asm volatile("mma.sync.aligned.m16n8k16.row.col.f32.bf16.bf16.f32 "
                 "{%0,%1,%2,%3}, {%4,%5,%6,%7}, {%8,%9}, {%0,%1,%2,%3};"
                 : "+f"(c[0]), "+f"(c[1]), "+f"(c[2]), "+f"(c[3])
                 : "r"(a[0]), "r"(a[1]), "r"(a[2]), "r"(a[3]), "r"(b[0]), "r"(b[1]));
}

// ---------------- weight pre-conversion ----------------
__global__ void k_wconv(const float* __restrict__ W0, const float* __restrict__ W1,
                        const float* __restrict__ W2, const float* __restrict__ W3,
                        const float* __restrict__ W4)
{
    int id = blockIdx.x * 256 + threadIdx.x;
    if (id >= 5 * 16384) return;
    int m = id >> 14, rem = id & 16383;
    int n = rem >> 7, k = rem & 127;
    const float* W = (m == 0) ? W0 : (m == 1) ? W1 : (m == 2) ? W2 : (m == 3) ? W3 : W4;
    float v = W[k * 128 + n];
    __nv_bfloat16 h = __float2bfloat16_rn(v);
    g_Wh[id] = h;
    g_Wl[id] = __float2bfloat16_rn(v - __bfloat162float(h));
}

// ---------------- HMMA GEMM core: 128x128 tile, 256 thr, 8 warps 64x32 ----------------
#define ASTR2 24
#define BSTR  136

struct __align__(16) SmemT {
    float Astg[2][128][16];             // fp32 A chunk staging
    __nv_bfloat16 Ah[2][128][ASTR2];    // chunk-local hi
    __nv_bfloat16 Al[2][128][ASTR2];    // chunk-local lo
    __nv_bfloat16 Bh[128][BSTR];        // full B [n][k] hi
    __nv_bfloat16 Bl[128][BSTR];        // full B lo
};
#define SMEM_T_BYTES (sizeof(SmemT))

template <bool SCALE>
__device__ __forceinline__ void run_gemm_mma(SmemT& S,
    const float* __restrict__ A,
    const __nv_bfloat16* __restrict__ Bh_g, const __nv_bfloat16* __restrict__ Bl_g,
    int row0, int M, int t, float acc[4][4][4])
{
    const int lane = t & 31, wid = t >> 5;
    const int wm = wid & 1, wn = wid >> 1;
#pragma unroll
    for (int i = 0; i < 4; i++)
#pragma unroll
        for (int j = 0; j < 4; j++)
#pragma unroll
            for (int q = 0; q < 4; q++) acc[i][j][q] = 0.f;

    // prologue: full B (hi+lo; 128 rows x 128 bf16 = 16 cp16 per row) + A chunk 0
#pragma unroll
    for (int i = t; i < 2048; i += 256) {
        int n = i >> 4, q = i & 15;
        cp16(smem_u32(&S.Bh[n][q * 8]), Bh_g + n * 128 + q * 8);
        cp16(smem_u32(&S.Bl[n][q * 8]), Bl_g + n * 128 + q * 8);
    }
#pragma unroll
    for (int i = t; i < 512; i += 256) {
        int r = i >> 2, q = i & 3;
        int gr = min(row0 + r, M - 1);
        cp16(smem_u32(&S.Astg[0][r][q * 4]), A + gr * HIDDEN + q * 4);
    }
    cp_commit();

    const int cr = t >> 1, cb = (t & 1) * 8;   // conversion assignment

    for (int c = 0; c < 8; c++) {
        if (c < 7) {
#pragma unroll
            for (int i = t; i < 512; i += 256) {
                int r = i >> 2, q = i & 3;
                int gr = min(row0 + r, M - 1);
                cp16(smem_u32(&S.Astg[(c + 1) & 1][r][q * 4]),
                     A + gr * HIDDEN + (c + 1) * 16 + q * 4);
            }
            cp_commit();
            cp_wait1();
        } else {
            cp_wait0();
        }
        __syncthreads();

        const int buf = c & 1;
        // convert fp32 staging -> hi/lo bf16 (8 values per thread)
        {
            float inv = 1.f;
            if (SCALE) {
                int gr = min(row0 + cr, M - 1);
                inv = __frcp_rn(fmaxf(g_s[gr * HEADS + c], 1e-9f));
            }
            float4 v0 = *(float4*)(&S.Astg[buf][cr][cb]);
            float4 v1 = *(float4*)(&S.Astg[buf][cr][cb + 4]);
            float vs[8] = {v0.x, v0.y, v0.z, v0.w, v1.x, v1.y, v1.z, v1.w};
#pragma unroll
            for (int j = 0; j < 8; j += 2) {
                float a0 = vs[j] * inv, a1 = vs[j + 1] * inv;
                __nv_bfloat16 h0 = __float2bfloat16_rn(a0);
                __nv_bfloat16 h1 = __float2bfloat16_rn(a1);
                __nv_bfloat16 l0 = __float2bfloat16_rn(a0 - __bfloat162float(h0));
                __nv_bfloat16 l1 = __float2bfloat16_rn(a1 - __bfloat162float(h1));
                *(__nv_bfloat162*)(&S.Ah[buf][cr][cb + j]) = __nv_bfloat162(h0, h1);
                *(__nv_bfloat162*)(&S.Al[buf][cr][cb + j]) = __nv_bfloat162(l0, l1);
            }
        }
        __syncthreads();

        // fragments + 3-product mma
        const int arow = lane & 15, acolh = (lane >> 4) * 8;
        const int brow = lane & 7,  bcolh = ((lane >> 3) & 1) * 8;
        uint32_t af[4][4], bh[4][2], bl[4][2];
#pragma unroll
        for (int mt = 0; mt < 4; mt++)
            ldmat_x4(af[mt], smem_u32(&S.Ah[buf][wm * 64 + mt * 16 + arow][acolh]));
#pragma unroll
        for (int nt = 0; nt < 4; nt++) {
            ldmat_x2(bh[nt], smem_u32(&S.Bh[wn * 32 + nt * 8 + brow][c * 16 + bcolh]));
            ldmat_x2(bl[nt], smem_u32(&S.Bl[wn * 32 + nt * 8 + brow][c * 16 + bcolh]));
        }
#pragma unroll
        for (int mt = 0; mt < 4; mt++)
#pragma unroll
            for (int nt = 0; nt < 4; nt++) mma16816(acc[mt][nt], af[mt], bh[nt]);
#pragma unroll
        for (int mt = 0; mt < 4; mt++)
#pragma unroll
            for (int nt = 0; nt < 4; nt++) mma16816(acc[mt][nt], af[mt], bl[nt]);
#pragma unroll
        for (int mt = 0; mt < 4; mt++)
            ldmat_x4(af[mt], smem_u32(&S.Al[buf][wm * 64 + mt * 16 + arow][acolh]));
#pragma unroll
        for (int mt = 0; mt < 4; mt++)
#pragma unroll
            for (int nt = 0; nt < 4; nt++) mma16816(acc[mt][nt], af[mt], bh[nt]);
        __syncthreads();
    }
}

// ================= QKV GEMM + fused scratch init =================
__global__ __launch_bounds__(256, 2) void gemm_qkv(
    const float* __restrict__ A,
    const float* __restrict__ bias0, const float* __restrict__ bias1, const float* __restrict__ bias2,
    float* __restrict__ out0, float* __restrict__ out1, float* __restrict__ out2,
    int M)
{
    extern __shared__ char raw[];
    SmemT& S = *(SmemT*)raw;

    {
        int nthr = gridDim.x * gridDim.y * 256;
        int gtid = (blockIdx.y * gridDim.x + blockIdx.x) * 256 + threadIdx.x;
        float4 z = make_float4(0.f, 0.f, 0.f, 0.f);
        for (int i = gtid; i < N_NODES * HIDDEN / 4; i += nthr) ((float4*)g_U)[i] = z;
        for (int i = gtid; i < N_NODES * HEADS / 4; i += nthr) ((float4*)g_s)[i] = z;
        for (int i = gtid; i < N_NODES * 3 / 4; i += nthr) ((float4*)g_disp)[i] = z;
    }

    const int mat = blockIdx.y;
    const float* bias = (mat == 0) ? bias0 : (mat == 1) ? bias1 : bias2;
    float*       out  = (mat == 0) ? out0  : (mat == 1) ? out1  : out2;

    const int t = threadIdx.x, lane = t & 31, wid = t >> 5;
    const int wm = wid & 1, wn = wid >> 1;
    const int row0 = blockIdx.x * 128;

    float acc[4][4][4];
    run_gemm_mma<false>(S, A, g_Wh + mat * 16384, g_Wl + mat * 16384, row0, M, t, acc);

#pragma unroll
    for (int mt = 0; mt < 4; mt++) {
#pragma unroll
        for (int half = 0; half < 2; half++) {
            int gr = row0 + wm * 64 + mt * 16 + half * 8 + (lane >> 2);
            if (gr >= M) continue;
#pragma unroll
            for (int nt = 0; nt < 4; nt++) {
                int col = wn * 32 + nt * 8 + (lane & 3) * 2;
                float z0 = acc[mt][nt][half * 2 + 0] + bias[col];
                float z1 = acc[mt][nt][half * 2 + 1] + bias[col + 1];
                *(float2*)(out + gr * HIDDEN + col) = make_float2(z0, z1);
            }
        }
    }
}

// ================= fused node epilogue =================
__global__ __launch_bounds__(256, 2) void k_node_out(
    const float* __restrict__ bo,
    const float* __restrict__ bg1,
    const float* __restrict__ Wg2, const float* __restrict__ bg2,
    const float* __restrict__ hres,
    float* __restrict__ out, int M)
{
    extern __shared__ char raw[];
    SmemT& S = *(SmemT*)raw;
    const int t = threadIdx.x, lane = t & 31, wid = t >> 5;
    const int wm = wid & 1, wn = wid >> 1;
    const int row0 = blockIdx.x * 128;

    float acc[4][4][4];

    // ---- stage 1: h_out = (g_U * rcp(s)) @ Wo + bo + h ----
    run_gemm_mma<true>(S, g_U, g_Wh + 3 * 16384, g_Wl + 3 * 16384, row0, M, t, acc);
#pragma unroll
    for (int mt = 0; mt < 4; mt++) {
#pragma unroll
        for (int half = 0; half < 2; half++) {
            int gr = row0 + wm * 64 + mt * 16 + half * 8 + (lane >> 2);
            if (gr >= M) continue;
#pragma unroll
            for (int nt = 0; nt < 4; nt++) {
                int col = wn * 32 + nt * 8 + (lane & 3) * 2;
                float2 r2 = *(const float2*)(hres + gr * HIDDEN + col);
                float z0 = acc[mt][nt][half * 2 + 0] + bo[col] + r2.x;
                float z1 = acc[mt][nt][half * 2 + 1] + bo[col + 1] + r2.y;
                *(float2*)(out + gr * HIDDEN + col) = make_float2(z0, z1);
            }
        }
    }
    __syncthreads();

    // ---- stage 2: t1 = silu(h_out @ Wg1 + bg1) ----
    run_gemm_mma<false>(S, out, g_Wh + 4 * 16384, g_Wl + 4 * 16384, row0, M, t, acc);

    // ---- stage 3: gate = tanh(t1 . Wg2 + bg2) ----
    float* sc = (float*)&S.Astg[0][0][0];   // reuse staging as [128][4] partials
    __syncthreads();
#pragma unroll
    for (int mt = 0; mt < 4; mt++) {
#pragma unroll
        for (int half = 0; half < 2; half++) {
            float p = 0.f;
#pragma unroll
            for (int nt = 0; nt < 4; nt++) {
                int col = wn * 32 + nt * 8 + (lane & 3) * 2;
                float t0 = acc[mt][nt][half * 2 + 0] + bg1[col];
                float t1 = acc[mt][nt][half * 2 + 1] + bg1[col + 1];
                t0 = t0 / (1.f + __expf(-t0));
                t1 = t1 / (1.f + __expf(-t1));
                p = fmaf(t0, Wg2[col], p);
                p = fmaf(t1, Wg2[col + 1], p);
            }
            p += __shfl_xor_sync(0xffffffffu, p, 1);
            p += __shfl_xor_sync(0xffffffffu, p, 2);
            if ((lane & 3) == 0) {
                int r = wm * 64 + mt * 16 + half * 8 + (lane >> 2);
                sc[r * 4 + wn] = p;
            }
        }
    }
    __syncthreads();
    if (t < 128) {
        int gr = row0 + t;
        if (gr < M) {
            float s = sc[t * 4] + sc[t * 4 + 1] + sc[t * 4 + 2] + sc[t * 4 + 3];
            g_gate[gr] = tanhf(s + bg2[0]);
        }
    }
}

// ---------------- x_out epilogue ----------------
__global__ void k_xout(const float* __restrict__ x, float* __restrict__ out)
{
    int i = blockIdx.x * blockDim.x + threadIdx.x;
    if (i >= N_NODES * 3) return;
    int node = i / 3;
    out[N_NODES * HIDDEN + i] = x[i] + g_gate[node] * g_disp[i];
}

// ---------------- warp-per-edge kernel (R15-proven) ----------------
__global__ __launch_bounds__(256) void k_edge(
    const int* __restrict__ src, const int* __restrict__ dst,
    const float* __restrict__ dist,
    const float* __restrict__ Wd, const float* __restrict__ bd)
{
    int e = (blockIdx.x * blockDim.x + threadIdx.x) >> 5;
    if (e >= N_EDGES) return;
    const int lane = threadIdx.x & 31;
    const int h = lane >> 2;

    int sn = src[e], dn = dst[e];

    float4 q4 = *(const float4*)(g_q + sn * HIDDEN + lane * 4);
    float4 k4 = *(const float4*)(g_k + dn * HIDDEN + lane * 4);
    float p = q4.x * k4.x + q4.y * k4.y + q4.z * k4.z + q4.w * k4.w;
    p += __shfl_xor_sync(0xffffffffu, p, 1);
    p += __shfl_xor_sync(0xffffffffu, p, 2);

    float dd = dist[e];
    float lg = p * 0.25f - (dd * dd * Wd[h] + bd[h]);
    float ex = __expf(lg);

    if ((lane & 3) == 0) {
        g_ex[e * 8 + h] = ex;
        asm volatile("red.global.add.f32 [%0], %1;"
                     :: "l"(g_s + sn * HEADS + h), "f"(ex) : "memory");
    }

    float4 v4 = *(const float4*)(g_v + dn * HIDDEN + lane * 4);
    float x0 = v4.x * ex, x1 = v4.y * ex, x2 = v4.z * ex, x3 = v4.w * ex;
    asm volatile("red.global.add.v4.f32 [%0], {%1,%2,%3,%4};"
                 :: "l"(g_U + sn * HIDDEN + lane * 4), "f"(x0), "f"(x1), "f"(x2), "f"(x3)
                 : "memory");
}

// ---------------- displacement scatter ----------------
__global__ void k_disp(const int* __restrict__ src, const int* __restrict__ dst,
                       const float* __restrict__ x)
{
    int e = blockIdx.x * blockDim.x + threadIdx.x;
    if (e >= N_EDGES) return;
    int sn = src[e], dn = dst[e];

    const float4* exp4 = (const float4*)(g_ex + e * 8);
    const float4* sp   = (const float4*)(g_s + sn * 8);
    float4 e0 = exp4[0], e1 = exp4[1];
    float4 s0 = sp[0],   s1 = sp[1];

    float wsum =
        e0.x / fmaxf(s0.x, 1e-9f) + e0.y / fmaxf(s0.y, 1e-9f) +
        e0.z / fmaxf(s0.z, 1e-9f) + e0.w / fmaxf(s0.w, 1e-9f) +
        e1.x / fmaxf(s1.x, 1e-9f) + e1.y / fmaxf(s1.y, 1e-9f) +
        e1.z / fmaxf(s1.z, 1e-9f) + e1.w / fmaxf(s1.w, 1e-9f);
    float wmean = wsum * 0.125f;

#pragma unroll
    for (int c = 0; c < 3; c++)
        atomicAdd(&g_disp[sn * 3 + c], (x[dn * 3 + c] - x[sn * 3 + c]) * wmean);
}

// ---------------- launch ----------------
extern "C" void kernel_launch(void* const* d_in, const int* in_sizes, int n_in,
                              void* d_out, int out_size)
{
    (void)in_sizes; (void)n_in; (void)out_size;
    const float* h    = (const float*)d_in[0];
    const float* x    = (const float*)d_in[1];
    const int*   src  = (const int*)  d_in[2];
    const int*   dst  = (const int*)  d_in[3];
    const float* dist = (const float*)d_in[4];
    const float* Wq = (const float*)d_in[5],  *bq = (const float*)d_in[6];
    const float* Wk = (const float*)d_in[7],  *bk = (const float*)d_in[8];
    const float* Wv = (const float*)d_in[9],  *bv = (const float*)d_in[10];
    const float* Wo = (const float*)d_in[11], *bo = (const float*)d_in[12];
    const float* Wd = (const float*)d_in[13], *bd = (const float*)d_in[14];
    const float* Wg1 = (const float*)d_in[15], *bg1 = (const float*)d_in[16];
    const float* Wg2 = (const float*)d_in[17], *bg2 = (const float*)d_in[18];
    float* out = (float*)d_out;

    void *pq, *pk, *pv;
    cudaGetSymbolAddress(&pq, g_q);
    cudaGetSymbolAddress(&pk, g_k);
    cudaGetSymbolAddress(&pv, g_v);
    float* fq = (float*)pq; float* fk = (float*)pk; float* fv = (float*)pv;

    static cudaStream_t s2 = nullptr;
    static cudaEvent_t ev_fork = nullptr, ev_join = nullptr;
    static bool attr_set = false;
    if (s2 == nullptr) {
        cudaStreamCreateWithFlags(&s2, cudaStreamNonBlocking);
        cudaEventCreateWithFlags(&ev_fork, cudaEventDisableTiming);
        cudaEventCreateWithFlags(&ev_join, cudaEventDisableTiming);
    }
    if (!attr_set) {
        cudaFuncSetAttribute(gemm_qkv, cudaFuncAttributeMaxDynamicSharedMemorySize, (int)SMEM_T_BYTES);
        cudaFuncSetAttribute(k_node_out, cudaFuncAttributeMaxDynamicSharedMemorySize, (int)SMEM_T_BYTES);
        attr_set = true;
    }

    const int B = 256;
    int gblocks = (N_NODES + 127) / 128;

    // weight pre-conversion (fp32 -> hi/lo bf16, [n][k])
    k_wconv<<<(5 * 16384 + B - 1) / B, B>>>(Wq, Wk, Wv, Wo, Wg1);

    // fused QKV projection + scratch zero-init
    {
        dim3 grid(gblocks, 3);
        gemm_qkv<<<grid, 256, SMEM_T_BYTES>>>(h, bq, bk, bv, fq, fk, fv, N_NODES);
    }

    // edge phase: warp per edge
    {
        long long nthreads = (long long)N_EDGES * 32;
        k_edge<<<(int)((nthreads + B - 1) / B), B>>>(src, dst, dist, Wd, bd);
    }

    // fork: k_disp on side stream
    cudaEventRecord(ev_fork, 0);
    cudaStreamWaitEvent(s2, ev_fork, 0);
    k_disp<<<(N_EDGES + B - 1) / B, B, 0, s2>>>(src, dst, x);
    cudaEventRecord(ev_join, s2);

    // fused node epilogue on main stream
    k_node_out<<<gblocks, 256, SMEM_T_BYTES>>>(bo, bg1, Wg2, bg2, h, out, N_NODES);

    cudaStreamWaitEvent(0, ev_join, 0);
    k_xout<<<(N_NODES * 3 + B - 1) / B, B>>>(x, out);
}